// round 12
// baseline (speedup 1.0000x reference)
#include <cuda_runtime.h>
#include <cuda_bf16.h>
#include <cstdint>

// WeightedEmbeddingBag: score[b,m,:] = sum_{n=start_m..end_m-1} emb[input[b,n],:] * psw[b,n]
//
// R12: one warp per bag; 256-bit gathers (ld.global.nc.v8.b32): 16 lanes x 32B
// cover one 512B row, so each warp-load fetches TWO rows (half-warp 0 = even
// row, half-warp 1 = odd row). Halves gather instructions + L1tex wavefronts.
// Epilogue merges the two half-warp partial sums via shfl_xor(16).
// Streams (idx/w/offsets/output) stay .cs evict-first (R11 win).
//
// Inputs: input int32 [B,N], per_sample_weights f32 [B,N],
//         offsets int32 [B,M], emb_weight f32 [VOCAB,D]. Output f32 [B,M,D].

#define BB 4096
#define NN 200
#define MM 26
#define DD 128
#define D4 (DD / 4)

struct V8 { float f[8]; };

__device__ __forceinline__ V8 ldg256(const float* p) {
    V8 v;
    asm volatile("ld.global.nc.v8.b32 {%0,%1,%2,%3,%4,%5,%6,%7}, [%8];"
                 : "=f"(v.f[0]), "=f"(v.f[1]), "=f"(v.f[2]), "=f"(v.f[3]),
                   "=f"(v.f[4]), "=f"(v.f[5]), "=f"(v.f[6]), "=f"(v.f[7])
                 : "l"(p));
    return v;
}

__global__ __launch_bounds__(128, 8)
void weighted_bag_kernel(const int* __restrict__ input,
                         const float* __restrict__ psw,
                         const int* __restrict__ offsets,
                         const float* __restrict__ emb,     // [VOCAB, D]
                         float4* __restrict__ out4)         // [B, M, D4]
{
    const int gw   = (blockIdx.x * blockDim.x + threadIdx.x) >> 5;
    const int lane = threadIdx.x & 31;
    if (gw >= BB * MM) return;
    const int b = gw / MM;
    const int m = gw - b * MM;

    const int half = lane >> 4;        // 0: even rows, 1: odd rows
    const int sub  = lane & 15;        // 32B column slice within a row

    const int* __restrict__ offs = offsets + b * MM;
    const int end   = __ldcs(&offs[m]) + 1;
    const int start = (m == 0) ? 0 : __ldcs(&offs[m - 1]) + 1;

    const int*   __restrict__ inp  = input + b * NN;
    const float* __restrict__ wrow = psw   + b * NN;

    float acc[8];
    #pragma unroll
    for (int k = 0; k < 8; ++k) acc[k] = 0.f;

    for (int base = start; base < end; base += 32) {
        // coalesced streaming prefetch of up to 32 (index, weight) pairs
        const int n_l = base + lane;
        int   my_idx = 0;
        float my_w   = 0.f;
        if (n_l < end) {
            my_idx = __ldcs(&inp[n_l]);
            my_w   = __ldcs(&wrow[n_l]);
        }
        const int cnt = min(32, end - base);   // lanes >= cnt hold idx=0, w=0

        // two rows per iteration: my half processes row (j + half)
        #pragma unroll 4
        for (int j = 0; j < cnt; j += 2) {
            const int   src = j + half;        // <= 32; padded lanes give w=0
            const int   idx = __shfl_sync(0xffffffffu, my_idx, src & 31);
            const float w   = __shfl_sync(0xffffffffu, my_w,   src & 31);

            const V8 v = ldg256(&emb[(long long)idx * DD + sub * 8]);  // 32B slice
            #pragma unroll
            for (int k = 0; k < 8; ++k)
                acc[k] = fmaf(w, v.f[k], acc[k]);
        }
    }

    // merge even-row (half 0) and odd-row (half 1) partial sums
    #pragma unroll
    for (int k = 0; k < 8; ++k)
        acc[k] += __shfl_xor_sync(0xffffffffu, acc[k], 16);

    // lanes 0..15 store their 32B slice (two float4 .cs stores); full 512B row
    if (half == 0) {
        float4 o0, o1;
        o0.x = acc[0]; o0.y = acc[1]; o0.z = acc[2]; o0.w = acc[3];
        o1.x = acc[4]; o1.y = acc[5]; o1.z = acc[6]; o1.w = acc[7];
        float4* orow = out4 + ((long long)b * MM + m) * D4;
        __stcs(&orow[sub * 2 + 0], o0);
        __stcs(&orow[sub * 2 + 1], o1);
    }
}

extern "C" void kernel_launch(void* const* d_in, const int* in_sizes, int n_in,
                              void* d_out, int out_size)
{
    const int*   input   = (const int*)  d_in[0];
    const float* psw     = (const float*)d_in[1];
    const int*   offsets = (const int*)  d_in[2];
    const float* emb     = (const float*)d_in[3];
    float4*      out4    = (float4*)d_out;

    // one warp per (batch, bag): 4096*26 = 106496 warps; 4 warps/block
    const int threads = 128;
    const long long warps = (long long)BB * MM;
    const int blocks = (int)((warps * 32 + threads - 1) / threads);
    weighted_bag_kernel<<<blocks, threads>>>(input, psw, offsets, emb, out4);
}